// round 13
// baseline (speedup 1.0000x reference)
#include <cuda_runtime.h>
#include <cstdint>
#include <cstddef>

#define K27     27
#define N_DOWN  40000
#define N_UP    160000
#define C_DOWN  128
#define C_SKIP  64
#define C_CAT   192
#define C_OUT   96

// sigma (16-block): stored[p] = ch (p>>2)%4 + 4*(p&3) group-wise:
//   sigma(p) = (p & ~15) + ((p&15)>>2) + ((p&3)<<2)   -> LDS.128 quads = 2 k8-steps
__device__ float g_up   [(size_t)N_UP * C_DOWN];           // deconv out; cols sigma-ordered
__device__ float g_downR[(size_t)N_DOWN * C_DOWN];         // tf32-RN, sigma-permuted
__device__ float g_skipR[(size_t)N_UP * C_SKIP];           // tf32-RN, sigma-permuted
__device__ float g_WdT  [(size_t)K27 * C_DOWN * C_DOWN];   // [k][n][p] = Wd[k][sigma(p)][sigma(n)]
__device__ float g_WcT  [(size_t)K27 * C_OUT  * C_CAT];    // [k][n][p] = Wc[k][sigma(p)][n]

// ---------------------------------------------------------------------------
// Helpers
// ---------------------------------------------------------------------------
__device__ __forceinline__ uint32_t smem_u32(const void* p) {
    uint32_t a;
    asm("{ .reg .u64 t; cvta.to.shared.u64 t, %1; cvt.u32.u64 %0, t; }" : "=r"(a) : "l"(p));
    return a;
}
__device__ __forceinline__ float to_tf32(float x) {
    float r;
    asm("cvt.rn.tf32.f32 %0, %1;" : "=f"(r) : "f"(x));
    return r;
}
__device__ __forceinline__ int sigma(int p) {     // stored pos -> channel (16-block)
    return (p & ~15) + ((p & 15) >> 2) + ((p & 3) << 2);
}
__device__ __forceinline__ void red_add_v4(float* p, float4 v) {
    asm volatile("red.global.add.v4.f32 [%0], {%1, %2, %3, %4};"
                 :: "l"(p), "f"(v.x), "f"(v.y), "f"(v.z), "f"(v.w) : "memory");
}
__device__ __forceinline__ void mma_tf32(float* c, float2 a01, float2 a23,
                                         float2 b01) {
    asm("mma.sync.aligned.m16n8k8.row.col.f32.tf32.tf32.f32 "
        "{%0,%1,%2,%3}, {%4,%5,%6,%7}, {%8,%9}, {%0,%1,%2,%3};"
        : "+f"(c[0]), "+f"(c[1]), "+f"(c[2]), "+f"(c[3])
        : "r"(__float_as_uint(a01.x)), "r"(__float_as_uint(a23.x)),
          "r"(__float_as_uint(a01.y)), "r"(__float_as_uint(a23.y)),
          "r"(__float_as_uint(b01.x)), "r"(__float_as_uint(b01.y)));
}
__device__ __forceinline__ void cp_async16(uint32_t dst, const void* src) {
    asm volatile("cp.async.cg.shared.global [%0], [%1], 16;" :: "r"(dst), "l"(src));
}
#define CP_COMMIT()  asm volatile("cp.async.commit_group;" ::: "memory")
#define CP_WAIT(n)   asm volatile("cp.async.wait_group %0;" :: "n"(n) : "memory")

// ---------------------------------------------------------------------------
// Fused prep kernel: zero(g_up,out) | round+sigma(down) | round+sigma(skip) |
// transpose+round(Wd,Wc). Range-split grid.
// ---------------------------------------------------------------------------
#define UP_F4    ((N_UP * C_DOWN) / 4)     // 5,120,000
#define OUT_F4   ((N_UP * C_OUT) / 4)      // 3,840,000
#define ZERO_F4  (UP_F4 + OUT_F4)          // 8,960,000
#define DOWN_F16 ((N_DOWN * C_DOWN) / 16)  // 320,000
#define SKIP_F16 ((N_UP * C_SKIP) / 16)    // 640,000
#define WD_ELEMS (K27 * C_DOWN * C_DOWN)   // 442,368
#define WC_ELEMS (K27 * C_OUT * C_CAT)     // 497,664
#define PREP_TOT (ZERO_F4 + DOWN_F16 + SKIP_F16 + WD_ELEMS + WC_ELEMS)  // 10,860,032

__global__ void __launch_bounds__(256) prep_kernel(
    float4* __restrict__ out4,
    const float4* __restrict__ down4, const float4* __restrict__ skip4,
    const float* __restrict__ Wd, const float* __restrict__ Wc)
{
    int i = blockIdx.x * 256 + threadIdx.x;    // grid exact = PREP_TOT/256
    if (i < ZERO_F4) {
        float4 z = make_float4(0.f, 0.f, 0.f, 0.f);
        if (i < UP_F4) reinterpret_cast<float4*>(g_up)[i] = z;
        else           out4[i - UP_F4] = z;
        return;
    }
    i -= ZERO_F4;
    if (i < DOWN_F16 + SKIP_F16) {             // sigma: 4x4 transpose per 16
        const float4* s4; float4* dst;
        int g16;
        if (i < DOWN_F16) { s4 = down4; dst = (float4*)g_downR; g16 = i; }
        else              { s4 = skip4; dst = (float4*)g_skipR; g16 = i - DOWN_F16; }
        float4 a = s4[4 * g16], b = s4[4 * g16 + 1],
               c = s4[4 * g16 + 2], d = s4[4 * g16 + 3];
        dst += 4 * g16;
        dst[0] = make_float4(to_tf32(a.x), to_tf32(b.x), to_tf32(c.x), to_tf32(d.x));
        dst[1] = make_float4(to_tf32(a.y), to_tf32(b.y), to_tf32(c.y), to_tf32(d.y));
        dst[2] = make_float4(to_tf32(a.z), to_tf32(b.z), to_tf32(c.z), to_tf32(d.z));
        dst[3] = make_float4(to_tf32(a.w), to_tf32(b.w), to_tf32(c.w), to_tf32(d.w));
        return;
    }
    i -= DOWN_F16 + SKIP_F16;
    if (i < WD_ELEMS) {
        int k = i / (C_DOWN * C_DOWN), r = i % (C_DOWN * C_DOWN);
        int n = r / C_DOWN, p = r % C_DOWN;
        g_WdT[i] = to_tf32(Wd[((size_t)k * C_DOWN + sigma(p)) * C_DOWN + sigma(n)]);
    } else {
        int j = i - WD_ELEMS;
        int k = j / (C_OUT * C_CAT), r = j % (C_OUT * C_CAT);
        int n = r / C_CAT, p = r % C_CAT;
        g_WcT[j] = to_tf32(Wc[((size_t)k * C_CAT + sigma(p)) * C_OUT + n]);
    }
}

__global__ void __launch_bounds__(256) relu_round_up_kernel() {
    int i = blockIdx.x * 256 + threadIdx.x;
    float4 v = reinterpret_cast<float4*>(g_up)[i];
    v.x = to_tf32(fmaxf(v.x, 0.f)); v.y = to_tf32(fmaxf(v.y, 0.f));
    v.z = to_tf32(fmaxf(v.z, 0.f)); v.w = to_tf32(fmaxf(v.w, 0.f));
    reinterpret_cast<float4*>(g_up)[i] = v;
}

// ---------------------------------------------------------------------------
// Deconv MMA (R12 config): D[128,128] = A[128,128] @ WdT[k]^T. 4 K-phases of
// 32, dbl-buf cp.async, single-sync pipeline. Stride 48 (sigma LDS.128 quads).
// 256 threads, 8 warps, warp tile 32x64, c[2][8][4]=64 regs. D at stride 132.
// grid=(313,27), 2 CTAs/SM -> 16 warps/SM.
// ---------------------------------------------------------------------------
#define D_S     48
#define D_AB_F  (128 * D_S)                        // 6144
#define D_IDX_F (4 * D_AB_F)                       // 24576
#define D_DP    132
#define D_SMEM  ((D_IDX_F + 256) * 4)              // 99,328 B

__global__ void __launch_bounds__(256, 2)
deconv_mma_kernel(const int* __restrict__ iin, const int* __restrict__ iout)
{
    extern __shared__ __align__(16) float sm[];
    const uint32_t sbase = smem_u32(sm);
    int* iidx = (int*)(sm + D_IDX_F);
    int* oidx = iidx + 128;

    const int tid = threadIdx.x, wid = tid >> 5, lane = tid & 31;
    const int g = lane >> 2, t4 = lane & 3;
    const int k = blockIdx.y;
    const int ebase = blockIdx.x * 128;
    const int nvalid = min(128, N_DOWN - ebase);

    const int* pin  = iin  + (size_t)k * N_DOWN + ebase;
    const int* pout = iout + (size_t)k * N_DOWN + ebase;
    if (tid < 128) {
        iidx[tid] = (tid < nvalid) ? pin[tid] : pin[0];
        oidx[tid] = (tid < nvalid) ? pout[tid] : -1;
    }
    __syncthreads();

    const char* Wk = (const char*)(g_WdT + (size_t)k * C_DOWN * C_DOWN);
    const char* Dn = (const char*)g_downR;
    const int mbase = (wid & 3) * 32;
    const int nbase = (wid >> 2) * 64;

    const int e8 = tid >> 3, sub16 = (tid & 7) * 16;
    uint32_t asrc[4], bsrc[4], cdst[4];
#pragma unroll
    for (int i = 0; i < 4; i++) {
        int e = e8 + 32 * i;
        asrc[i] = (uint32_t)iidx[e] * 512u;
        bsrc[i] = (uint32_t)e * 512u;
        cdst[i] = (uint32_t)e * (D_S * 4) + sub16;
    }

    auto issue = [&](int p, int buf) {
        uint32_t aB = sbase + buf * (D_AB_F * 4);
        uint32_t bB = sbase + (2 + buf) * (D_AB_F * 4);
        const char* as = Dn + p * 128 + sub16;
        const char* bs = Wk + p * 128 + sub16;
#pragma unroll
        for (int i = 0; i < 4; i++) cp_async16(aB + cdst[i], as + asrc[i]);
#pragma unroll
        for (int i = 0; i < 4; i++) cp_async16(bB + cdst[i], bs + bsrc[i]);
        CP_COMMIT();
    };

    issue(0, 0);

    float c[2][8][4] = {};
#pragma unroll
    for (int p = 0; p < 4; p++) {
        CP_WAIT(0);
        __syncthreads();
        if (p < 3) issue(p + 1, (p + 1) & 1);

        const float* Ab = sm + (p & 1) * D_AB_F + (mbase + g) * D_S + 4 * t4;
        const float* Bb = sm + (2 + (p & 1)) * D_AB_F + (nbase + g) * D_S + 4 * t4;
#pragma unroll
        for (int t = 0; t < 2; t++) {
            const int kk = t * 16;
            float4 A0[2], A8[2];
#pragma unroll
            for (int mt = 0; mt < 2; mt++) {
                A0[mt] = *(const float4*)(Ab + mt * 16 * D_S + kk);
                A8[mt] = *(const float4*)(Ab + (mt * 16 + 8) * D_S + kk);
            }
#pragma unroll
            for (int j = 0; j < 8; j++) {
                float4 Bq = *(const float4*)(Bb + j * 8 * D_S + kk);
                mma_tf32(c[0][j], make_float2(A0[0].x, A0[0].y),
                                  make_float2(A8[0].x, A8[0].y),
                                  make_float2(Bq.x, Bq.y));
                mma_tf32(c[1][j], make_float2(A0[1].x, A0[1].y),
                                  make_float2(A8[1].x, A8[1].y),
                                  make_float2(Bq.x, Bq.y));
                mma_tf32(c[0][j], make_float2(A0[0].z, A0[0].w),
                                  make_float2(A8[0].z, A8[0].w),
                                  make_float2(Bq.z, Bq.w));
                mma_tf32(c[1][j], make_float2(A0[1].z, A0[1].w),
                                  make_float2(A8[1].z, A8[1].w),
                                  make_float2(Bq.z, Bq.w));
            }
        }
    }
    __syncthreads();

    // Stage D (stride 132)
#pragma unroll
    for (int mt = 0; mt < 2; mt++) {
        int row = mbase + mt * 16 + g;
#pragma unroll
        for (int j = 0; j < 8; j++) {
            int col = nbase + j * 8 + 2 * t4;
            *(float2*)&sm[row * D_DP + col]       = make_float2(c[mt][j][0], c[mt][j][1]);
            *(float2*)&sm[(row + 8) * D_DP + col] = make_float2(c[mt][j][2], c[mt][j][3]);
        }
    }
    __syncthreads();

    // Scatter: 4096 f4, 16/thread
#pragma unroll
    for (int t = 0; t < 16; t++) {
        int f = tid + t * 256;
        int e = f >> 5, q = f & 31;
        int o = oidx[e];
        if (o >= 0) {
            float4 v = *(float4*)&sm[e * D_DP + q * 4];
            red_add_v4(g_up + (size_t)o * C_DOWN + q * 4, v);
        }
    }
}

// ---------------------------------------------------------------------------
// Conv MMA: D[128,96] = relu_cat[128,192] @ WcT[k]^T. 6 K-phases of 32,
// dbl-buf cp.async, single-sync pipeline. Stride 48 (sigma LDS.128 quads).
// 256 threads, 8 warps, thin warp tile 32x48 (4M x 2N), c[2][6][4]=48 regs.
// D staged at stride 100. grid=(1250,27), 2 CTAs/SM -> 16 warps/SM.
// ---------------------------------------------------------------------------
#define C_S     48
#define C_AB_F  (128 * C_S)                        // 6144
#define C_BB_F  (96 * C_S)                         // 4608
#define C_IDX_F (2 * C_AB_F + 2 * C_BB_F)          // 21504
#define C_DP    100
#define C_SMEM  ((C_IDX_F + 256) * 4)              // 87,040 B

__global__ void __launch_bounds__(256, 2)
conv_mma_kernel(const int* __restrict__ iin, const int* __restrict__ iout,
                float* __restrict__ out)
{
    extern __shared__ __align__(16) float sm[];
    const uint32_t sbase = smem_u32(sm);
    const uint32_t aB[2] = { sbase, sbase + C_AB_F * 4 };
    const uint32_t bB[2] = { sbase + 2 * C_AB_F * 4, sbase + (2 * C_AB_F + C_BB_F) * 4 };
    int* iidx = (int*)(sm + C_IDX_F);
    int* oidx = iidx + 128;

    const int tid = threadIdx.x, wid = tid >> 5, lane = tid & 31;
    const int g = lane >> 2, t4 = lane & 3;
    const int k = blockIdx.y;
    const int ebase = blockIdx.x * 128;

    const int* pin  = iin  + (size_t)k * N_UP + ebase;
    const int* pout = iout + (size_t)k * N_UP + ebase;
    if (tid < 128) {
        iidx[tid] = pin[tid];
        oidx[tid] = pout[tid];
    }
    __syncthreads();

    const char* Wk = (const char*)(g_WcT + (size_t)k * C_OUT * C_CAT);
    const char* Up = (const char*)g_up;
    const char* Sk = (const char*)g_skipR;
    const int mbase = (wid & 3) * 32;
    const int nbase = (wid >> 2) * 48;

    // Gather precompute: A 1024 chunks (4/thread), B 768 chunks (3/thread)
    const int e8 = tid >> 3, sub16 = (tid & 7) * 16;
    uint32_t aoff[4], adst[4], boff[3], bdst[3];
#pragma unroll
    for (int i = 0; i < 4; i++) {
        int e = e8 + 32 * i;
        aoff[i] = (uint32_t)iidx[e] * 512u;
        adst[i] = (uint32_t)e * (C_S * 4) + sub16;
    }
#pragma unroll
    for (int i = 0; i < 3; i++) {
        int n = e8 + 32 * i;
        boff[i] = (uint32_t)n * (C_CAT * 4);
        bdst[i] = (uint32_t)n * (C_S * 4) + sub16;
    }

    auto issue = [&](int p, int buf) {
        if (p < 4) {
            const char* as = Up + p * 128 + sub16;
#pragma unroll
            for (int i = 0; i < 4; i++) cp_async16(aB[buf] + adst[i], as + aoff[i]);
        } else {
            const char* as = Sk + (p - 4) * 128 + sub16;
#pragma unroll
            for (int i = 0; i < 4; i++) cp_async16(aB[buf] + adst[i], as + (aoff[i] >> 1));
        }
        const char* bs = Wk + p * 128 + sub16;
#pragma unroll
        for (int i = 0; i < 3; i++) cp_async16(bB[buf] + bdst[i], bs + boff[i]);
        CP_COMMIT();
    };

    issue(0, 0);

    float c[2][6][4] = {};
#pragma unroll
    for (int p = 0; p < 6; p++) {
        CP_WAIT(0);
        __syncthreads();            // phase-p data visible AND compute(p-1) done
        if (p < 5) issue(p + 1, (p + 1) & 1);

        const float* Ab = sm + (p & 1) * C_AB_F + (mbase + g) * C_S + 4 * t4;
        const float* Bb = sm + 2 * C_AB_F + (p & 1) * C_BB_F + (nbase + g) * C_S + 4 * t4;
#pragma unroll
        for (int t = 0; t < 2; t++) {           // two k16 quad-blocks per phase
            const int kk = t * 16;
            float4 A0[2], A8[2];
#pragma unroll
            for (int mt = 0; mt < 2; mt++) {
                A0[mt] = *(const float4*)(Ab + mt * 16 * C_S + kk);
                A8[mt] = *(const float4*)(Ab + (mt * 16 + 8) * C_S + kk);
            }
#pragma unroll
            for (int j = 0; j < 6; j++) {
                float4 Bq = *(const float4*)(Bb + j * 8 * C_S + kk);
                mma_tf32(c[0][j], make_float2(A0[0].x, A0[0].y),
                                  make_float2(A8[0].x, A8[0].y),
                                  make_float2(Bq.x, Bq.y));
                mma_tf32(c[1][j], make_float2(A0[1].x, A0[1].y),
                                  make_float2(A8[1].x, A8[1].y),
                                  make_float2(Bq.x, Bq.y));
                mma_tf32(c[0][j], make_float2(A0[0].z, A0[0].w),
                                  make_float2(A8[0].z, A8[0].w),
                                  make_float2(Bq.z, Bq.w));
                mma_tf32(c[1][j], make_float2(A0[1].z, A0[1].w),
                                  make_float2(A8[1].z, A8[1].w),
                                  make_float2(Bq.z, Bq.w));
            }
        }
    }
    __syncthreads();                // all compute done before D staging reuses sm

    // Stage D (stride 100)
#pragma unroll
    for (int mt = 0; mt < 2; mt++) {
        int row = mbase + mt * 16 + g;
#pragma unroll
        for (int j = 0; j < 6; j++) {
            int col = nbase + j * 8 + 2 * t4;
            *(float2*)&sm[row * C_DP + col]       = make_float2(c[mt][j][0], c[mt][j][1]);
            *(float2*)&sm[(row + 8) * C_DP + col] = make_float2(c[mt][j][2], c[mt][j][3]);
        }
    }
    __syncthreads();

    // Scatter: 3072 f4, 12/thread
#pragma unroll
    for (int t = 0; t < 12; t++) {
        int f = tid + t * 256;
        int e = f / 24, q = f % 24;
        float4 v = *(float4*)&sm[e * C_DP + q * 4];
        red_add_v4(out + (size_t)oidx[e] * C_OUT + q * 4, v);
    }
}

// ---------------------------------------------------------------------------
// Final ReLU
// ---------------------------------------------------------------------------
__global__ void __launch_bounds__(256) relu_kernel(float4* __restrict__ out4) {
    int i = blockIdx.x * 256 + threadIdx.x;
    float4 v = out4[i];
    v.x = fmaxf(v.x, 0.f); v.y = fmaxf(v.y, 0.f);
    v.z = fmaxf(v.z, 0.f); v.w = fmaxf(v.w, 0.f);
    out4[i] = v;
}

// ---------------------------------------------------------------------------
// Launch
// ---------------------------------------------------------------------------
extern "C" void kernel_launch(void* const* d_in, const int* in_sizes, int n_in,
                              void* d_out, int out_size)
{
    const float* skip = nullptr; const float* down = nullptr;
    const float* Wd = nullptr;   const float* Wc = nullptr;
    const int *d_iin = nullptr, *d_iout = nullptr, *c_iin = nullptr, *c_iout = nullptr;

    for (int i = 0; i < n_in; i++) {
        int sz = in_sizes[i];
        if      (sz == N_UP * C_SKIP)         skip = (const float*)d_in[i];
        else if (sz == N_DOWN * C_DOWN)       down = (const float*)d_in[i];
        else if (sz == K27 * C_DOWN * C_DOWN) Wd   = (const float*)d_in[i];
        else if (sz == K27 * C_CAT * C_OUT)   Wc   = (const float*)d_in[i];
        else if (sz == K27 * N_DOWN) { if (!d_iin) d_iin = (const int*)d_in[i]; else d_iout = (const int*)d_in[i]; }
        else if (sz == K27 * N_UP)   { if (!c_iin) c_iin = (const int*)d_in[i]; else c_iout = (const int*)d_in[i]; }
    }
    float* out = (float*)d_out;

    cudaFuncSetAttribute(deconv_mma_kernel, cudaFuncAttributeMaxDynamicSharedMemorySize, D_SMEM);
    cudaFuncSetAttribute(conv_mma_kernel,   cudaFuncAttributeMaxDynamicSharedMemorySize, C_SMEM);

    prep_kernel<<<PREP_TOT / 256, 256>>>((float4*)out, (const float4*)down,
                                         (const float4*)skip, Wd, Wc);
    deconv_mma_kernel<<<dim3((N_DOWN + 127) / 128, K27), 256, D_SMEM>>>(d_iin, d_iout);
    relu_round_up_kernel<<<UP_F4 / 256, 256>>>();
    conv_mma_kernel<<<dim3(N_UP / 128, K27), 256, C_SMEM>>>(c_iin, c_iout, out);
    relu_kernel<<<OUT_F4 / 256, 256>>>((float4*)out);
}

// round 14
// speedup vs baseline: 1.5106x; 1.5106x over previous
#include <cuda_runtime.h>
#include <cuda_fp16.h>
#include <cstdint>
#include <cstddef>

#define K27     27
#define N_DOWN  40000
#define N_UP    160000
#define C_DOWN  128
#define C_SKIP  64
#define C_CAT   192
#define C_OUT   96

// Deconv (tf32, unchanged R12): sigma (16-block): sigma(4a+b) = a+4b
// Conv (fp16): pi (16-block): stored[4t+r] = k{2t,2t+1,2t+8,2t+9}[r]
//   -> one LDS.64 per m16n8k16 fragment half
__device__ float  g_up   [(size_t)N_UP * C_DOWN];          // deconv accum (f32, sigma cols)
__device__ float  g_downR[(size_t)N_DOWN * C_DOWN];        // tf32-RN, sigma
__device__ float  g_WdT  [(size_t)K27 * C_DOWN * C_DOWN];  // [k][n][p]=Wd[k][sig(p)][sig(n)]
__device__ __half g_upH  [(size_t)N_UP * C_DOWN];          // relu(fp16), pi cols
__device__ __half g_skH  [(size_t)N_UP * C_SKIP];          // fp16, pi cols
__device__ __half g_WcH  [(size_t)K27 * C_OUT * C_CAT];    // [k][n][p]=Wc[k][pi(p)][n], fp16

// ---------------------------------------------------------------------------
// Helpers
// ---------------------------------------------------------------------------
__device__ __forceinline__ uint32_t smem_u32(const void* p) {
    uint32_t a;
    asm("{ .reg .u64 t; cvta.to.shared.u64 t, %1; cvt.u32.u64 %0, t; }" : "=r"(a) : "l"(p));
    return a;
}
__device__ __forceinline__ float to_tf32(float x) {
    float r;
    asm("cvt.rn.tf32.f32 %0, %1;" : "=f"(r) : "f"(x));
    return r;
}
__device__ __forceinline__ int sigma(int p) {
    return (p & ~15) + ((p & 15) >> 2) + ((p & 3) << 2);
}
__device__ __forceinline__ uint32_t pack_h2(float lo, float hi) {
    uint32_t u = ((uint32_t)__half_as_ushort(__float2half_rn(hi)) << 16)
               |  (uint32_t)__half_as_ushort(__float2half_rn(lo));
    return u;
}
__device__ __forceinline__ void red_add_v4(float* p, float4 v) {
    asm volatile("red.global.add.v4.f32 [%0], {%1, %2, %3, %4};"
                 :: "l"(p), "f"(v.x), "f"(v.y), "f"(v.z), "f"(v.w) : "memory");
}
__device__ __forceinline__ void mma_tf32(float* c, float2 a01, float2 a23,
                                         float2 b01) {
    asm("mma.sync.aligned.m16n8k8.row.col.f32.tf32.tf32.f32 "
        "{%0,%1,%2,%3}, {%4,%5,%6,%7}, {%8,%9}, {%0,%1,%2,%3};"
        : "+f"(c[0]), "+f"(c[1]), "+f"(c[2]), "+f"(c[3])
        : "r"(__float_as_uint(a01.x)), "r"(__float_as_uint(a23.x)),
          "r"(__float_as_uint(a01.y)), "r"(__float_as_uint(a23.y)),
          "r"(__float_as_uint(b01.x)), "r"(__float_as_uint(b01.y)));
}
__device__ __forceinline__ void mma_f16(float* c, uint32_t a0, uint32_t a1,
                                        uint32_t a2, uint32_t a3,
                                        uint32_t b0, uint32_t b1) {
    asm("mma.sync.aligned.m16n8k16.row.col.f32.f16.f16.f32 "
        "{%0,%1,%2,%3}, {%4,%5,%6,%7}, {%8,%9}, {%0,%1,%2,%3};"
        : "+f"(c[0]), "+f"(c[1]), "+f"(c[2]), "+f"(c[3])
        : "r"(a0), "r"(a1), "r"(a2), "r"(a3), "r"(b0), "r"(b1));
}
__device__ __forceinline__ void cp_async16(uint32_t dst, const void* src) {
    asm volatile("cp.async.cg.shared.global [%0], [%1], 16;" :: "r"(dst), "l"(src));
}
#define CP_COMMIT()  asm volatile("cp.async.commit_group;" ::: "memory")
#define CP_WAIT(n)   asm volatile("cp.async.wait_group %0;" :: "n"(n) : "memory")

// ---------------------------------------------------------------------------
// Fused prep: zero(g_up,out) | round+sigma(down,f32) | fp16+pi(skip) |
// transpose Wd (tf32/sigma) | transpose Wc (fp16/pi)
// ---------------------------------------------------------------------------
#define UP_F4    ((N_UP * C_DOWN) / 4)     // 5,120,000
#define OUT_F4   ((N_UP * C_OUT) / 4)      // 3,840,000
#define ZERO_F4  (UP_F4 + OUT_F4)          // 8,960,000
#define DOWN_F16 ((N_DOWN * C_DOWN) / 16)  // 320,000
#define SKIP_B16 ((N_UP * C_SKIP) / 16)    // 640,000
#define WD_ELEMS (K27 * C_DOWN * C_DOWN)   // 442,368
#define WC_ELEMS (K27 * C_OUT * C_CAT)     // 497,664
#define PREP_TOT (ZERO_F4 + DOWN_F16 + SKIP_B16 + WD_ELEMS + WC_ELEMS) // 10,860,032

__global__ void __launch_bounds__(256) prep_kernel(
    float4* __restrict__ out4,
    const float4* __restrict__ down4, const float4* __restrict__ skip4,
    const float* __restrict__ Wd, const float* __restrict__ Wc)
{
    const int P[16] = {0,1,8,9, 2,3,10,11, 4,5,12,13, 6,7,14,15};   // pi
    int i = blockIdx.x * 256 + threadIdx.x;
    if (i < ZERO_F4) {
        float4 z = make_float4(0.f, 0.f, 0.f, 0.f);
        if (i < UP_F4) reinterpret_cast<float4*>(g_up)[i] = z;
        else           out4[i - UP_F4] = z;
        return;
    }
    i -= ZERO_F4;
    if (i < DOWN_F16) {                        // down: sigma f32 (4x4 transpose)
        float4 a = down4[4 * i], b = down4[4 * i + 1],
               c = down4[4 * i + 2], d = down4[4 * i + 3];
        float4* dst = (float4*)g_downR + 4 * i;
        dst[0] = make_float4(to_tf32(a.x), to_tf32(b.x), to_tf32(c.x), to_tf32(d.x));
        dst[1] = make_float4(to_tf32(a.y), to_tf32(b.y), to_tf32(c.y), to_tf32(d.y));
        dst[2] = make_float4(to_tf32(a.z), to_tf32(b.z), to_tf32(c.z), to_tf32(d.z));
        dst[3] = make_float4(to_tf32(a.w), to_tf32(b.w), to_tf32(c.w), to_tf32(d.w));
        return;
    }
    i -= DOWN_F16;
    if (i < SKIP_B16) {                        // skip: fp16, pi-permuted 16-block
        float v[16];
        float4 a = skip4[4 * i], b = skip4[4 * i + 1],
               c = skip4[4 * i + 2], d = skip4[4 * i + 3];
        v[0]=a.x; v[1]=a.y; v[2]=a.z; v[3]=a.w;
        v[4]=b.x; v[5]=b.y; v[6]=b.z; v[7]=b.w;
        v[8]=c.x; v[9]=c.y; v[10]=c.z; v[11]=c.w;
        v[12]=d.x; v[13]=d.y; v[14]=d.z; v[15]=d.w;
        uint32_t r[8];
#pragma unroll
        for (int j = 0; j < 8; j++) r[j] = pack_h2(v[P[2*j]], v[P[2*j+1]]);
        uint4* o = (uint4*)((char*)g_skH + (size_t)i * 32);
        o[0] = make_uint4(r[0], r[1], r[2], r[3]);
        o[1] = make_uint4(r[4], r[5], r[6], r[7]);
        return;
    }
    i -= SKIP_B16;
    if (i < WD_ELEMS) {
        int k = i / (C_DOWN * C_DOWN), r = i % (C_DOWN * C_DOWN);
        int n = r / C_DOWN, p = r % C_DOWN;
        g_WdT[i] = to_tf32(Wd[((size_t)k * C_DOWN + sigma(p)) * C_DOWN + sigma(n)]);
    } else {
        int j = i - WD_ELEMS;
        int k = j / (C_OUT * C_CAT), r = j % (C_OUT * C_CAT);
        int n = r / C_CAT, p = r % C_CAT;
        int pp = (p & ~15) + P[p & 15];
        g_WcH[j] = __float2half_rn(Wc[((size_t)k * C_CAT + pp) * C_OUT + n]);
    }
}

// relu + fp16 + sigma->pi remap: g_upH[q] = fp16(relu(g_up[M[q]])) per 16-block
#define UP_B16 ((N_UP * C_DOWN) / 16)              // 1,280,000
__global__ void __launch_bounds__(256) relu_half_up_kernel() {
    const int M[16] = {0,4,2,6, 8,12,10,14, 1,5,3,7, 9,13,11,15};  // sigma(pi(q))
    int i = blockIdx.x * 256 + threadIdx.x;
    const float4* in4 = (const float4*)g_up + 4 * (size_t)i;
    float v[16];
    float4 a = in4[0], b = in4[1], c = in4[2], d = in4[3];
    v[0]=a.x; v[1]=a.y; v[2]=a.z; v[3]=a.w;
    v[4]=b.x; v[5]=b.y; v[6]=b.z; v[7]=b.w;
    v[8]=c.x; v[9]=c.y; v[10]=c.z; v[11]=c.w;
    v[12]=d.x; v[13]=d.y; v[14]=d.z; v[15]=d.w;
    uint32_t r[8];
#pragma unroll
    for (int j = 0; j < 8; j++)
        r[j] = pack_h2(fmaxf(v[M[2*j]], 0.f), fmaxf(v[M[2*j+1]], 0.f));
    uint4* o = (uint4*)((char*)g_upH + (size_t)i * 32);
    o[0] = make_uint4(r[0], r[1], r[2], r[3]);
    o[1] = make_uint4(r[4], r[5], r[6], r[7]);
}

// ---------------------------------------------------------------------------
// Deconv MMA (R12, unchanged): tf32, sigma LDS.128 quads, stride 48.
// 256 threads, 8 warps, warp tile 32x64. 2 CTAs/SM.
// ---------------------------------------------------------------------------
#define D_S     48
#define D_AB_F  (128 * D_S)
#define D_IDX_F (4 * D_AB_F)
#define D_DP    132
#define D_SMEM  ((D_IDX_F + 256) * 4)

__global__ void __launch_bounds__(256, 2)
deconv_mma_kernel(const int* __restrict__ iin, const int* __restrict__ iout)
{
    extern __shared__ __align__(16) float sm[];
    const uint32_t sbase = smem_u32(sm);
    int* iidx = (int*)(sm + D_IDX_F);
    int* oidx = iidx + 128;

    const int tid = threadIdx.x, wid = tid >> 5, lane = tid & 31;
    const int g = lane >> 2, t4 = lane & 3;
    const int k = blockIdx.y;
    const int ebase = blockIdx.x * 128;
    const int nvalid = min(128, N_DOWN - ebase);

    const int* pin  = iin  + (size_t)k * N_DOWN + ebase;
    const int* pout = iout + (size_t)k * N_DOWN + ebase;
    if (tid < 128) {
        iidx[tid] = (tid < nvalid) ? pin[tid] : pin[0];
        oidx[tid] = (tid < nvalid) ? pout[tid] : -1;
    }
    __syncthreads();

    const char* Wk = (const char*)(g_WdT + (size_t)k * C_DOWN * C_DOWN);
    const char* Dn = (const char*)g_downR;
    const int mbase = (wid & 3) * 32;
    const int nbase = (wid >> 2) * 64;

    const int e8 = tid >> 3, sub16 = (tid & 7) * 16;
    uint32_t asrc[4], bsrc[4], cdst[4];
#pragma unroll
    for (int i = 0; i < 4; i++) {
        int e = e8 + 32 * i;
        asrc[i] = (uint32_t)iidx[e] * 512u;
        bsrc[i] = (uint32_t)e * 512u;
        cdst[i] = (uint32_t)e * (D_S * 4) + sub16;
    }

    auto issue = [&](int p, int buf) {
        uint32_t aB = sbase + buf * (D_AB_F * 4);
        uint32_t bB = sbase + (2 + buf) * (D_AB_F * 4);
        const char* as = Dn + p * 128 + sub16;
        const char* bs = Wk + p * 128 + sub16;
#pragma unroll
        for (int i = 0; i < 4; i++) cp_async16(aB + cdst[i], as + asrc[i]);
#pragma unroll
        for (int i = 0; i < 4; i++) cp_async16(bB + cdst[i], bs + bsrc[i]);
        CP_COMMIT();
    };

    issue(0, 0);

    float c[2][8][4] = {};
#pragma unroll
    for (int p = 0; p < 4; p++) {
        CP_WAIT(0);
        __syncthreads();
        if (p < 3) issue(p + 1, (p + 1) & 1);

        const float* Ab = sm + (p & 1) * D_AB_F + (mbase + g) * D_S + 4 * t4;
        const float* Bb = sm + (2 + (p & 1)) * D_AB_F + (nbase + g) * D_S + 4 * t4;
#pragma unroll
        for (int t = 0; t < 2; t++) {
            const int kk = t * 16;
            float4 A0[2], A8[2];
#pragma unroll
            for (int mt = 0; mt < 2; mt++) {
                A0[mt] = *(const float4*)(Ab + mt * 16 * D_S + kk);
                A8[mt] = *(const float4*)(Ab + (mt * 16 + 8) * D_S + kk);
            }
#pragma unroll
            for (int j = 0; j < 8; j++) {
                float4 Bq = *(const float4*)(Bb + j * 8 * D_S + kk);
                mma_tf32(c[0][j], make_float2(A0[0].x, A0[0].y),
                                  make_float2(A8[0].x, A8[0].y),
                                  make_float2(Bq.x, Bq.y));
                mma_tf32(c[1][j], make_float2(A0[1].x, A0[1].y),
                                  make_float2(A8[1].x, A8[1].y),
                                  make_float2(Bq.x, Bq.y));
                mma_tf32(c[0][j], make_float2(A0[0].z, A0[0].w),
                                  make_float2(A8[0].z, A8[0].w),
                                  make_float2(Bq.z, Bq.w));
                mma_tf32(c[1][j], make_float2(A0[1].z, A0[1].w),
                                  make_float2(A8[1].z, A8[1].w),
                                  make_float2(Bq.z, Bq.w));
            }
        }
    }
    __syncthreads();

#pragma unroll
    for (int mt = 0; mt < 2; mt++) {
        int row = mbase + mt * 16 + g;
#pragma unroll
        for (int j = 0; j < 8; j++) {
            int col = nbase + j * 8 + 2 * t4;
            *(float2*)&sm[row * D_DP + col]       = make_float2(c[mt][j][0], c[mt][j][1]);
            *(float2*)&sm[(row + 8) * D_DP + col] = make_float2(c[mt][j][2], c[mt][j][3]);
        }
    }
    __syncthreads();

#pragma unroll
    for (int t = 0; t < 16; t++) {
        int f = tid + t * 256;
        int e = f >> 5, q = f & 31;
        int o = oidx[e];
        if (o >= 0) {
            float4 v = *(float4*)&sm[e * D_DP + q * 4];
            red_add_v4(g_up + (size_t)o * C_DOWN + q * 4, v);
        }
    }
}

// ---------------------------------------------------------------------------
// Conv MMA (fp16): D[128,96] = relu_cat[128,192] @ WcH[k]^T.
// 4 K-phases of 48 halves, dbl-buf cp.async, pi-layout LDS.64 fragments,
// row stride 96 B (24 words, conflict-free). 128 threads, 4 warps, fat warp
// tile 64x48, m16n8k16 mma, c[4][6][4]=96 regs. D staged at stride 100,
// v4 red scatter. grid=(1250,27), 3 CTAs/SM.
// ---------------------------------------------------------------------------
#define CH_ROWB 96
#define CA_B    (128 * CH_ROWB)            // 12288 B
#define CB_B    (96 * CH_ROWB)             // 9216 B
#define C_DP    100
#define C_STAGE_B (128 * C_DP * 4)         // 51200 B
#define C_SMEM  (C_STAGE_B + 1024)         // 52224 B

__global__ void __launch_bounds__(128, 3)
conv_mma_kernel(const int* __restrict__ iin, const int* __restrict__ iout,
                float* __restrict__ out)
{
    extern __shared__ __align__(16) char smc[];
    float* sm = (float*)smc;
    const uint32_t sbase = smem_u32(smc);
    const uint32_t aB[2] = { sbase, sbase + CA_B };
    const uint32_t bB[2] = { sbase + 2 * CA_B, sbase + 2 * CA_B + CB_B };
    int* iidx = (int*)(smc + C_STAGE_B);
    int* oidx = iidx + 128;

    const int tid = threadIdx.x, wid = tid >> 5, lane = tid & 31;
    const int g = lane >> 2, t4 = lane & 3;
    const int k = blockIdx.y;
    const int ebase = blockIdx.x * 128;

    const int* pin  = iin  + (size_t)k * N_UP + ebase;
    const int* pout = iout + (size_t)k * N_UP + ebase;
    iidx[tid] = pin[tid];
    oidx[tid] = pout[tid];
    __syncthreads();

    const char* WcHk = (const char*)g_WcH + (size_t)k * C_OUT * C_CAT * 2;
    const char* UpH  = (const char*)g_upH;
    const char* SkH  = (const char*)g_skH;
    const int mbase = (wid & 1) * 64;
    const int nbase = (wid >> 1) * 48;

    // Gather precompute. A: 768 chunks (6/thread), B: 576 chunks (<=5/thread)
    uint32_t aoffU[6], adst[6]; int cAoff[6];
#pragma unroll
    for (int i = 0; i < 6; i++) {
        int ch = tid + i * 128;
        int e = ch / 6, c = ch % 6;
        aoffU[i] = (uint32_t)iidx[e] * 256u;       // upH row bytes
        adst[i]  = (uint32_t)e * CH_ROWB + c * 16;
        cAoff[i] = c * 16;
    }
    uint32_t bsrc[5], bdst[5];
#pragma unroll
    for (int i = 0; i < 5; i++) {
        int ch = tid + i * 128;
        if (ch < 576) {
            int n = ch / 6, c = ch % 6;
            bsrc[i] = (uint32_t)n * 384 + c * 16;  // WcHk row = 384 B
            bdst[i] = (uint32_t)n * CH_ROWB + c * 16;
        } else bsrc[i] = 0xFFFFFFFFu;
    }

    auto issue = [&](int p, int buf) {
        const int pb = p * 96;                     // byte offset in 384B cat-row
#pragma unroll
        for (int i = 0; i < 6; i++) {
            int sb = pb + cAoff[i];
            const char* src = (sb < 256) ? UpH + aoffU[i] + sb
                                         : SkH + (aoffU[i] >> 1) + (sb - 256);
            cp_async16(aB[buf] + adst[i], src);
        }
#pragma unroll
        for (int i = 0; i < 5; i++)
            if (bsrc[i] != 0xFFFFFFFFu)
                cp_async16(bB[buf] + bdst[i], WcHk + bsrc[i] + pb);
        CP_COMMIT();
    };

    issue(0, 0);

    float c[4][6][4] = {};
#pragma unroll
    for (int p = 0; p < 4; p++) {
        CP_WAIT(0);
        __syncthreads();
        if (p < 3) issue(p + 1, (p + 1) & 1);

        const char* Ab = smc + (p & 1) * CA_B + (mbase + g) * CH_ROWB + t4 * 8;
        const char* Bb = smc + 2 * CA_B + (p & 1) * CB_B + (nbase + g) * CH_ROWB + t4 * 8;
#pragma unroll
        for (int s = 0; s < 3; s++) {              // three k16 steps per phase
            const int kb = s * 32;
            uint2 au[4], al[4];
#pragma unroll
            for (int mt = 0; mt < 4; mt++) {
                au[mt] = *(const uint2*)(Ab + mt * 16 * CH_ROWB + kb);
                al[mt] = *(const uint2*)(Ab + (mt * 16 + 8) * CH_ROWB + kb);
            }
#pragma unroll
            for (int j = 0; j < 6; j++) {
                uint2 b = *(const uint2*)(Bb + j * 8 * CH_ROWB + kb);
#pragma unroll
                for (int mt = 0; mt < 4; mt++)
                    mma_f16(c[mt][j], au[mt].x, al[mt].x, au[mt].y, al[mt].y,
                            b.x, b.y);
            }
        }
    }
    __syncthreads();

    // Stage D (stride 100)
#pragma unroll
    for (int mt = 0; mt < 4; mt++) {
        int row = mbase + mt * 16 + g;
#pragma unroll
        for (int j = 0; j < 6; j++) {
            int col = nbase + j * 8 + 2 * t4;
            *(float2*)&sm[row * C_DP + col]       = make_float2(c[mt][j][0], c[mt][j][1]);
            *(float2*)&sm[(row + 8) * C_DP + col] = make_float2(c[mt][j][2], c[mt][j][3]);
        }
    }
    __syncthreads();

    // Scatter: 3072 f4, 24/thread
#pragma unroll
    for (int t = 0; t < 24; t++) {
        int f = tid + t * 128;
        int e = f / 24, q = f % 24;
        float4 v = *(float4*)&sm[e * C_DP + q * 4];
        red_add_v4(out + (size_t)oidx[e] * C_OUT + q * 4, v);
    }
}

// ---------------------------------------------------------------------------
// Final ReLU
// ---------------------------------------------------------------------------
__global__ void __launch_bounds__(256) relu_kernel(float4* __restrict__ out4) {
    int i = blockIdx.x * 256 + threadIdx.x;
    float4 v = out4[i];
    v.x = fmaxf(v.x, 0.f); v.y = fmaxf(v.y, 0.f);
    v.z = fmaxf(v.z, 0.f); v.w = fmaxf(v.w, 0.f);
    out4[i] = v;
}

// ---------------------------------------------------------------------------
// Launch
// ---------------------------------------------------------------------------
extern "C" void kernel_launch(void* const* d_in, const int* in_sizes, int n_in,
                              void* d_out, int out_size)
{
    const float* skip = nullptr; const float* down = nullptr;
    const float* Wd = nullptr;   const float* Wc = nullptr;
    const int *d_iin = nullptr, *d_iout = nullptr, *c_iin = nullptr, *c_iout = nullptr;

    for (int i = 0; i < n_in; i++) {
        int sz = in_sizes[i];
        if      (sz == N_UP * C_SKIP)         skip = (const float*)d_in[i];
        else if (sz == N_DOWN * C_DOWN)       down = (const float*)d_in[i];
        else if (sz == K27 * C_DOWN * C_DOWN) Wd   = (const float*)d_in[i];
        else if (sz == K27 * C_CAT * C_OUT)   Wc   = (const float*)d_in[i];
        else if (sz == K27 * N_DOWN) { if (!d_iin) d_iin = (const int*)d_in[i]; else d_iout = (const int*)d_in[i]; }
        else if (sz == K27 * N_UP)   { if (!c_iin) c_iin = (const int*)d_in[i]; else c_iout = (const int*)d_in[i]; }
    }
    float* out = (float*)d_out;

    cudaFuncSetAttribute(deconv_mma_kernel, cudaFuncAttributeMaxDynamicSharedMemorySize, D_SMEM);
    cudaFuncSetAttribute(conv_mma_kernel,   cudaFuncAttributeMaxDynamicSharedMemorySize, C_SMEM);

    prep_kernel<<<PREP_TOT / 256, 256>>>((float4*)out, (const float4*)down,
                                         (const float4*)skip, Wd, Wc);
    deconv_mma_kernel<<<dim3((N_DOWN + 127) / 128, K27), 256, D_SMEM>>>(d_iin, d_iout);
    relu_half_up_kernel<<<UP_B16 / 256, 256>>>();
    conv_mma_kernel<<<dim3(N_UP / 128, K27), 128, C_SMEM>>>(c_iin, c_iout, out);
    relu_kernel<<<OUT_F4 / 256, 256>>>((float4*)out);
}

// round 15
// speedup vs baseline: 1.5625x; 1.0343x over previous
#include <cuda_runtime.h>
#include <cuda_fp16.h>
#include <cstdint>
#include <cstddef>

#define K27     27
#define N_DOWN  40000
#define N_UP    160000
#define C_DOWN  128
#define C_SKIP  64
#define C_CAT   192
#define C_OUT   96

// pi (16-block): stored[q] holds channel PI[q], PI = {0,1,8,9, 2,3,10,11,
// 4,5,12,13, 6,7,14,15}. One LDS.64 = one m16n8k16 fragment half.
__device__ float  g_up   [(size_t)N_UP * C_DOWN];          // deconv accum (f32, pi cols)
__device__ __half g_downH[(size_t)N_DOWN * C_DOWN];        // fp16, pi cols
__device__ __half g_WdH  [(size_t)K27 * C_DOWN * C_DOWN];  // [k][n][p]=Wd[k][pi(p)][pi(n)]
__device__ __half g_upH  [(size_t)N_UP * C_DOWN];          // relu(fp16), pi cols
__device__ __half g_skH  [(size_t)N_UP * C_SKIP];          // fp16, pi cols
__device__ __half g_WcH  [(size_t)K27 * C_OUT * C_CAT];    // [k][n][p]=Wc[k][pi(p)][n]

// ---------------------------------------------------------------------------
// Helpers
// ---------------------------------------------------------------------------
__device__ __forceinline__ uint32_t smem_u32(const void* p) {
    uint32_t a;
    asm("{ .reg .u64 t; cvta.to.shared.u64 t, %1; cvt.u32.u64 %0, t; }" : "=r"(a) : "l"(p));
    return a;
}
__device__ __forceinline__ uint32_t pack_h2(float lo, float hi) {
    return ((uint32_t)__half_as_ushort(__float2half_rn(hi)) << 16)
         |  (uint32_t)__half_as_ushort(__float2half_rn(lo));
}
__device__ __forceinline__ void red_add_v4(float* p, float4 v) {
    asm volatile("red.global.add.v4.f32 [%0], {%1, %2, %3, %4};"
                 :: "l"(p), "f"(v.x), "f"(v.y), "f"(v.z), "f"(v.w) : "memory");
}
__device__ __forceinline__ void mma_f16(float* c, uint32_t a0, uint32_t a1,
                                        uint32_t a2, uint32_t a3,
                                        uint32_t b0, uint32_t b1) {
    asm("mma.sync.aligned.m16n8k16.row.col.f32.f16.f16.f32 "
        "{%0,%1,%2,%3}, {%4,%5,%6,%7}, {%8,%9}, {%0,%1,%2,%3};"
        : "+f"(c[0]), "+f"(c[1]), "+f"(c[2]), "+f"(c[3])
        : "r"(a0), "r"(a1), "r"(a2), "r"(a3), "r"(b0), "r"(b1));
}
__device__ __forceinline__ void cp_async16(uint32_t dst, const void* src) {
    asm volatile("cp.async.cg.shared.global [%0], [%1], 16;" :: "r"(dst), "l"(src));
}
#define CP_COMMIT()  asm volatile("cp.async.commit_group;" ::: "memory")
#define CP_WAIT(n)   asm volatile("cp.async.wait_group %0;" :: "n"(n) : "memory")

// ---------------------------------------------------------------------------
// Fused prep: zero(g_up,out) | fp16+pi(down) | fp16+pi(skip) |
// Wd -> fp16 (pi,pi) | Wc -> fp16 (pi on p)
// ---------------------------------------------------------------------------
#define UP_F4    ((N_UP * C_DOWN) / 4)     // 5,120,000
#define OUT_F4   ((N_UP * C_OUT) / 4)      // 3,840,000
#define ZERO_F4  (UP_F4 + OUT_F4)          // 8,960,000
#define DOWN_B16 ((N_DOWN * C_DOWN) / 16)  // 320,000
#define SKIP_B16 ((N_UP * C_SKIP) / 16)    // 640,000
#define WD_ELEMS (K27 * C_DOWN * C_DOWN)   // 442,368
#define WC_ELEMS (K27 * C_OUT * C_CAT)     // 497,664
#define PREP_TOT (ZERO_F4 + DOWN_B16 + SKIP_B16 + WD_ELEMS + WC_ELEMS) // 10,860,032

__global__ void __launch_bounds__(256) prep_kernel(
    float4* __restrict__ out4,
    const float4* __restrict__ down4, const float4* __restrict__ skip4,
    const float* __restrict__ Wd, const float* __restrict__ Wc)
{
    const int P[16] = {0,1,8,9, 2,3,10,11, 4,5,12,13, 6,7,14,15};   // pi
    int i = blockIdx.x * 256 + threadIdx.x;
    if (i < ZERO_F4) {
        float4 z = make_float4(0.f, 0.f, 0.f, 0.f);
        if (i < UP_F4) reinterpret_cast<float4*>(g_up)[i] = z;
        else           out4[i - UP_F4] = z;
        return;
    }
    i -= ZERO_F4;
    if (i < DOWN_B16 + SKIP_B16) {             // fp16, pi-permuted 16-block
        const float4* s4; __half* dstH; int g16;
        if (i < DOWN_B16) { s4 = down4; dstH = g_downH; g16 = i; }
        else              { s4 = skip4; dstH = g_skH;   g16 = i - DOWN_B16; }
        float v[16];
        float4 a = s4[4 * g16], b = s4[4 * g16 + 1],
               c = s4[4 * g16 + 2], d = s4[4 * g16 + 3];
        v[0]=a.x; v[1]=a.y; v[2]=a.z; v[3]=a.w;
        v[4]=b.x; v[5]=b.y; v[6]=b.z; v[7]=b.w;
        v[8]=c.x; v[9]=c.y; v[10]=c.z; v[11]=c.w;
        v[12]=d.x; v[13]=d.y; v[14]=d.z; v[15]=d.w;
        uint32_t r[8];
#pragma unroll
        for (int j = 0; j < 8; j++) r[j] = pack_h2(v[P[2*j]], v[P[2*j+1]]);
        uint4* o = (uint4*)((char*)dstH + (size_t)g16 * 32);
        o[0] = make_uint4(r[0], r[1], r[2], r[3]);
        o[1] = make_uint4(r[4], r[5], r[6], r[7]);
        return;
    }
    i -= DOWN_B16 + SKIP_B16;
    if (i < WD_ELEMS) {
        int k = i / (C_DOWN * C_DOWN), r = i % (C_DOWN * C_DOWN);
        int n = r / C_DOWN, p = r % C_DOWN;
        int pp = (p & ~15) + P[p & 15];
        int nn = (n & ~15) + P[n & 15];
        g_WdH[i] = __float2half_rn(Wd[((size_t)k * C_DOWN + pp) * C_DOWN + nn]);
    } else {
        int j = i - WD_ELEMS;
        int k = j / (C_OUT * C_CAT), r = j % (C_OUT * C_CAT);
        int n = r / C_CAT, p = r % C_CAT;
        int pp = (p & ~15) + P[p & 15];
        g_WcH[j] = __float2half_rn(Wc[((size_t)k * C_CAT + pp) * C_OUT + n]);
    }
}

// relu + fp16 (g_up is already pi-ordered; no permutation needed)
#define UP_B16 ((N_UP * C_DOWN) / 16)              // 1,280,000
__global__ void __launch_bounds__(256) relu_half_up_kernel() {
    int i = blockIdx.x * 256 + threadIdx.x;
    const float4* in4 = (const float4*)g_up + 4 * (size_t)i;
    uint32_t r[8];
#pragma unroll
    for (int j = 0; j < 4; j++) {
        float4 v = in4[j];
        r[2*j]   = pack_h2(fmaxf(v.x, 0.f), fmaxf(v.y, 0.f));
        r[2*j+1] = pack_h2(fmaxf(v.z, 0.f), fmaxf(v.w, 0.f));
    }
    uint4* o = (uint4*)((char*)g_upH + (size_t)i * 32);
    o[0] = make_uint4(r[0], r[1], r[2], r[3]);
    o[1] = make_uint4(r[4], r[5], r[6], r[7]);
}

// ---------------------------------------------------------------------------
// Deconv MMA (fp16): D[128,128] = A[128,128] @ WdH[k]^T. 2 K-phases of 64
// halves (128 B row-chunks), dbl-buf cp.async, pi-layout LDS.64 fragments,
// row stride 144 B (36 words, conflict-free). 256 threads, 8 warps, warp tile
// 32x64, m16n8k16 mma, c[2][8][4]=64 regs. D staged at stride 132 f32,
// v4 red scatter. grid=(313,27), 2 CTAs/SM.
// ---------------------------------------------------------------------------
#define DH_ROWB 144
#define DA_B    (128 * DH_ROWB)            // 18432 B
#define D_IDX_B (4 * DA_B)                 // 73728 B
#define D_DP    132
#define D_SMEM  (D_IDX_B + 1024)           // 74752 B

__global__ void __launch_bounds__(256, 2)
deconv_mma_kernel(const int* __restrict__ iin, const int* __restrict__ iout)
{
    extern __shared__ __align__(16) char smd[];
    float* sm = (float*)smd;
    const uint32_t sbase = smem_u32(smd);
    int* iidx = (int*)(smd + D_IDX_B);
    int* oidx = iidx + 128;

    const int tid = threadIdx.x, wid = tid >> 5, lane = tid & 31;
    const int g = lane >> 2, t4 = lane & 3;
    const int k = blockIdx.y;
    const int ebase = blockIdx.x * 128;
    const int nvalid = min(128, N_DOWN - ebase);

    const int* pin  = iin  + (size_t)k * N_DOWN + ebase;
    const int* pout = iout + (size_t)k * N_DOWN + ebase;
    if (tid < 128) {
        iidx[tid] = (tid < nvalid) ? pin[tid] : pin[0];
        oidx[tid] = (tid < nvalid) ? pout[tid] : -1;
    }
    __syncthreads();

    const char* WdHk = (const char*)g_WdH + (size_t)k * C_DOWN * C_DOWN * 2;
    const char* DnH  = (const char*)g_downH;
    const int mbase = (wid & 3) * 32;
    const int nbase = (wid >> 2) * 64;

    // A/B: 1024 16B-chunks per phase each (128 rows x 8), 4/thread each
    const int e8 = tid >> 3, sub16 = (tid & 7) * 16;
    uint32_t asrc[4], bsrc[4], cdst[4];
#pragma unroll
    for (int i = 0; i < 4; i++) {
        int e = e8 + 32 * i;
        asrc[i] = (uint32_t)iidx[e] * 256u;        // downH row = 256 B
        bsrc[i] = (uint32_t)e * 256u;              // WdH row = 256 B
        cdst[i] = (uint32_t)e * DH_ROWB + sub16;
    }

    auto issue = [&](int p, int buf) {
        uint32_t aB = sbase + buf * DA_B;
        uint32_t bB = sbase + (2 + buf) * DA_B;
        const char* as = DnH  + p * 128 + sub16;
        const char* bs = WdHk + p * 128 + sub16;
#pragma unroll
        for (int i = 0; i < 4; i++) cp_async16(aB + cdst[i], as + asrc[i]);
#pragma unroll
        for (int i = 0; i < 4; i++) cp_async16(bB + cdst[i], bs + bsrc[i]);
        CP_COMMIT();
    };

    issue(0, 0);

    float c[2][8][4] = {};
#pragma unroll
    for (int p = 0; p < 2; p++) {
        CP_WAIT(0);
        __syncthreads();
        if (p < 1) issue(1, 1);

        const char* Ab = smd + (p & 1) * DA_B + (mbase + g) * DH_ROWB + t4 * 8;
        const char* Bb = smd + (2 + (p & 1)) * DA_B + (nbase + g) * DH_ROWB + t4 * 8;
#pragma unroll
        for (int s = 0; s < 4; s++) {              // four k16 steps per phase
            const int kb = s * 32;
            uint2 au[2], al[2];
#pragma unroll
            for (int mt = 0; mt < 2; mt++) {
                au[mt] = *(const uint2*)(Ab + mt * 16 * DH_ROWB + kb);
                al[mt] = *(const uint2*)(Ab + (mt * 16 + 8) * DH_ROWB + kb);
            }
#pragma unroll
            for (int j = 0; j < 8; j++) {
                uint2 b = *(const uint2*)(Bb + j * 8 * DH_ROWB + kb);
                mma_f16(c[0][j], au[0].x, al[0].x, au[0].y, al[0].y, b.x, b.y);
                mma_f16(c[1][j], au[1].x, al[1].x, au[1].y, al[1].y, b.x, b.y);
            }
        }
    }
    __syncthreads();

    // Stage D (f32, stride 132) over buffer region
#pragma unroll
    for (int mt = 0; mt < 2; mt++) {
        int row = mbase + mt * 16 + g;
#pragma unroll
        for (int j = 0; j < 8; j++) {
            int col = nbase + j * 8 + 2 * t4;
            *(float2*)&sm[row * D_DP + col]       = make_float2(c[mt][j][0], c[mt][j][1]);
            *(float2*)&sm[(row + 8) * D_DP + col] = make_float2(c[mt][j][2], c[mt][j][3]);
        }
    }
    __syncthreads();

    // Scatter: 4096 f4, 16/thread
#pragma unroll
    for (int t = 0; t < 16; t++) {
        int f = tid + t * 256;
        int e = f >> 5, q = f & 31;
        int o = oidx[e];
        if (o >= 0) {
            float4 v = *(float4*)&sm[e * D_DP + q * 4];
            red_add_v4(g_up + (size_t)o * C_DOWN + q * 4, v);
        }
    }
}

// ---------------------------------------------------------------------------
// Conv MMA (fp16, R14 unchanged): D[128,96] = relu_cat[128,192] @ WcH[k]^T.
// 4 K-phases of 48 halves, dbl-buf cp.async, pi LDS.64, row stride 96 B.
// 128 threads, 4 warps, fat warp tile 64x48, c[4][6][4]=96 regs. D staged at
// stride 100, v4 red scatter. grid=(1250,27), 3 CTAs/SM.
// ---------------------------------------------------------------------------
#define CH_ROWB 96
#define CA_B    (128 * CH_ROWB)            // 12288 B
#define CB_B    (96 * CH_ROWB)             // 9216 B
#define C_DP    100
#define C_STAGE_B (128 * C_DP * 4)         // 51200 B
#define C_SMEM  (C_STAGE_B + 1024)         // 52224 B

__global__ void __launch_bounds__(128, 3)
conv_mma_kernel(const int* __restrict__ iin, const int* __restrict__ iout,
                float* __restrict__ out)
{
    extern __shared__ __align__(16) char smc[];
    float* sm = (float*)smc;
    const uint32_t sbase = smem_u32(smc);
    const uint32_t aB[2] = { sbase, sbase + CA_B };
    const uint32_t bB[2] = { sbase + 2 * CA_B, sbase + 2 * CA_B + CB_B };
    int* iidx = (int*)(smc + C_STAGE_B);
    int* oidx = iidx + 128;

    const int tid = threadIdx.x, wid = tid >> 5, lane = tid & 31;
    const int g = lane >> 2, t4 = lane & 3;
    const int k = blockIdx.y;
    const int ebase = blockIdx.x * 128;

    const int* pin  = iin  + (size_t)k * N_UP + ebase;
    const int* pout = iout + (size_t)k * N_UP + ebase;
    iidx[tid] = pin[tid];
    oidx[tid] = pout[tid];
    __syncthreads();

    const char* WcHk = (const char*)g_WcH + (size_t)k * C_OUT * C_CAT * 2;
    const char* UpH  = (const char*)g_upH;
    const char* SkH  = (const char*)g_skH;
    const int mbase = (wid & 1) * 64;
    const int nbase = (wid >> 1) * 48;

    uint32_t aoffU[6], adst[6]; int cAoff[6];
#pragma unroll
    for (int i = 0; i < 6; i++) {
        int ch = tid + i * 128;
        int e = ch / 6, c = ch % 6;
        aoffU[i] = (uint32_t)iidx[e] * 256u;
        adst[i]  = (uint32_t)e * CH_ROWB + c * 16;
        cAoff[i] = c * 16;
    }
    uint32_t bsrc[5], bdst[5];
#pragma unroll
    for (int i = 0; i < 5; i++) {
        int ch = tid + i * 128;
        if (ch < 576) {
            int n = ch / 6, c = ch % 6;
            bsrc[i] = (uint32_t)n * 384 + c * 16;
            bdst[i] = (uint32_t)n * CH_ROWB + c * 16;
        } else bsrc[i] = 0xFFFFFFFFu;
    }

    auto issue = [&](int p, int buf) {
        const int pb = p * 96;
#pragma unroll
        for (int i = 0; i < 6; i++) {
            int sb = pb + cAoff[i];
            const char* src = (sb < 256) ? UpH + aoffU[i] + sb
                                         : SkH + (aoffU[i] >> 1) + (sb - 256);
            cp_async16(aB[buf] + adst[i], src);
        }
#pragma unroll
        for (int i = 0; i < 5; i++)
            if (bsrc[i] != 0xFFFFFFFFu)
                cp_async16(bB[buf] + bdst[i], WcHk + bsrc[i] + pb);
        CP_COMMIT();
    };

    issue(0, 0);

    float c[4][6][4] = {};
#pragma unroll
    for (int p = 0; p < 4; p++) {
        CP_WAIT(0);
        __syncthreads();
        if (p < 3) issue(p + 1, (p + 1) & 1);

        const char* Ab = smc + (p & 1) * CA_B + (mbase + g) * CH_ROWB + t4 * 8;
        const char* Bb = smc + 2 * CA_B + (p & 1) * CB_B + (nbase + g) * CH_ROWB + t4 * 8;
#pragma unroll
        for (int s = 0; s < 3; s++) {
            const int kb = s * 32;
            uint2 au[4], al[4];
#pragma unroll
            for (int mt = 0; mt < 4; mt++) {
                au[mt] = *(const uint2*)(Ab + mt * 16 * CH_ROWB + kb);
                al[mt] = *(const uint2*)(Ab + (mt * 16 + 8) * CH_ROWB + kb);
            }
#pragma unroll
            for (int j = 0; j < 6; j++) {
                uint2 b = *(const uint2*)(Bb + j * 8 * CH_ROWB + kb);
#pragma unroll
                for (int mt = 0; mt < 4; mt++)
                    mma_f16(c[mt][j], au[mt].x, al[mt].x, au[mt].y, al[mt].y,
                            b.x, b.y);
            }
        }
    }
    __syncthreads();

#pragma unroll
    for (int mt = 0; mt < 4; mt++) {
        int row = mbase + mt * 16 + g;
#pragma unroll
        for (int j = 0; j < 6; j++) {
            int col = nbase + j * 8 + 2 * t4;
            *(float2*)&sm[row * C_DP + col]       = make_float2(c[mt][j][0], c[mt][j][1]);
            *(float2*)&sm[(row + 8) * C_DP + col] = make_float2(c[mt][j][2], c[mt][j][3]);
        }
    }
    __syncthreads();

#pragma unroll
    for (int t = 0; t < 24; t++) {
        int f = tid + t * 128;
        int e = f / 24, q = f % 24;
        float4 v = *(float4*)&sm[e * C_DP + q * 4];
        red_add_v4(out + (size_t)oidx[e] * C_OUT + q * 4, v);
    }
}

// ---------------------------------------------------------------------------
// Final ReLU
// ---------------------------------------------------------------------------
__global__ void __launch_bounds__(256) relu_kernel(float4* __restrict__ out4) {
    int i = blockIdx.x * 256 + threadIdx.x;
    float4 v = out4[i];
    v.x = fmaxf(v.x, 0.f); v.y = fmaxf(v.y, 0.f);
    v.z = fmaxf(v.z, 0.f); v.w = fmaxf(v.w, 0.f);
    out4[i] = v;
}

// ---------------------------------------------------------------------------
// Launch
// ---------------------------------------------------------------------------
extern "C" void kernel_launch(void* const* d_in, const int* in_sizes, int n_in,
                              void* d_out, int out_size)
{
    const float* skip = nullptr; const float* down = nullptr;
    const float* Wd = nullptr;   const float* Wc = nullptr;
    const int *d_iin = nullptr, *d_iout = nullptr, *c_iin = nullptr, *c_iout = nullptr;

    for (int i = 0; i < n_in; i++) {
        int sz = in_sizes[i];
        if      (sz == N_UP * C_SKIP)         skip = (const float*)d_in[i];
        else if (sz == N_DOWN * C_DOWN)       down = (const float*)d_in[i];
        else if (sz == K27 * C_DOWN * C_DOWN) Wd   = (const float*)d_in[i];
        else if (sz == K27 * C_CAT * C_OUT)   Wc   = (const float*)d_in[i];
        else if (sz == K27 * N_DOWN) { if (!d_iin) d_iin = (const int*)d_in[i]; else d_iout = (const int*)d_in[i]; }
        else if (sz == K27 * N_UP)   { if (!c_iin) c_iin = (const int*)d_in[i]; else c_iout = (const int*)d_in[i]; }
    }
    float* out = (float*)d_out;

    cudaFuncSetAttribute(deconv_mma_kernel, cudaFuncAttributeMaxDynamicSharedMemorySize, D_SMEM);
    cudaFuncSetAttribute(conv_mma_kernel,   cudaFuncAttributeMaxDynamicSharedMemorySize, C_SMEM);

    prep_kernel<<<PREP_TOT / 256, 256>>>((float4*)out, (const float4*)down,
                                         (const float4*)skip, Wd, Wc);
    deconv_mma_kernel<<<dim3((N_DOWN + 127) / 128, K27), 256, D_SMEM>>>(d_iin, d_iout);
    relu_half_up_kernel<<<UP_B16 / 256, 256>>>();
    conv_mma_kernel<<<dim3(N_UP / 128, K27), 128, C_SMEM>>>(c_iin, c_iout, out);
    relu_kernel<<<OUT_F4 / 256, 256>>>((float4*)out);
}

// round 16
// speedup vs baseline: 1.5943x; 1.0204x over previous
#include <cuda_runtime.h>
#include <cuda_fp16.h>
#include <cstdint>
#include <cstddef>

#define K27     27
#define N_DOWN  40000
#define N_UP    160000
#define C_DOWN  128
#define C_SKIP  64
#define C_CAT   192
#define C_OUT   96

// pi (16-block): stored[q] holds channel PI[q], PI = {0,1,8,9, 2,3,10,11,
// 4,5,12,13, 6,7,14,15}. One LDS.64 = one m16n8k16 fragment half.
__device__ float  g_up   [(size_t)N_UP * C_DOWN];          // deconv accum (f32, pi cols)
__device__ __half g_downH[(size_t)N_DOWN * C_DOWN];        // fp16, pi cols
__device__ __half g_WdH  [(size_t)K27 * C_DOWN * C_DOWN];  // [k][n][p]=Wd[k][pi(p)][pi(n)]
__device__ __half g_upH  [(size_t)N_UP * C_DOWN];          // relu(fp16), pi cols
__device__ __half g_skH  [(size_t)N_UP * C_SKIP];          // fp16, pi cols
__device__ __half g_WcH  [(size_t)K27 * C_OUT * C_CAT];    // [k][n][p]=Wc[k][pi(p)][n]

// ---------------------------------------------------------------------------
// Helpers
// ---------------------------------------------------------------------------
__device__ __forceinline__ uint32_t smem_u32(const void* p) {
    uint32_t a;
    asm("{ .reg .u64 t; cvta.to.shared.u64 t, %1; cvt.u32.u64 %0, t; }" : "=r"(a) : "l"(p));
    return a;
}
__device__ __forceinline__ uint32_t pack_h2(float lo, float hi) {
    return ((uint32_t)__half_as_ushort(__float2half_rn(hi)) << 16)
         |  (uint32_t)__half_as_ushort(__float2half_rn(lo));
}
__device__ __forceinline__ void red_add_v4(float* p, float4 v) {
    asm volatile("red.global.add.v4.f32 [%0], {%1, %2, %3, %4};"
                 :: "l"(p), "f"(v.x), "f"(v.y), "f"(v.z), "f"(v.w) : "memory");
}
__device__ __forceinline__ void mma_f16(float* c, uint32_t a0, uint32_t a1,
                                        uint32_t a2, uint32_t a3,
                                        uint32_t b0, uint32_t b1) {
    asm("mma.sync.aligned.m16n8k16.row.col.f32.f16.f16.f32 "
        "{%0,%1,%2,%3}, {%4,%5,%6,%7}, {%8,%9}, {%0,%1,%2,%3};"
        : "+f"(c[0]), "+f"(c[1]), "+f"(c[2]), "+f"(c[3])
        : "r"(a0), "r"(a1), "r"(a2), "r"(a3), "r"(b0), "r"(b1));
}
__device__ __forceinline__ void cp_async16(uint32_t dst, const void* src) {
    asm volatile("cp.async.cg.shared.global [%0], [%1], 16;" :: "r"(dst), "l"(src));
}
#define CP_COMMIT()  asm volatile("cp.async.commit_group;" ::: "memory")
#define CP_WAIT(n)   asm volatile("cp.async.wait_group %0;" :: "n"(n) : "memory")

// ---------------------------------------------------------------------------
// Fused prep: zero(g_up,out) | fp16+pi(down) | fp16+pi(skip) |
// Wd -> fp16 (pi,pi) | Wc -> fp16 (pi on p)
// ---------------------------------------------------------------------------
#define UP_F4    ((N_UP * C_DOWN) / 4)     // 5,120,000
#define OUT_F4   ((N_UP * C_OUT) / 4)      // 3,840,000
#define ZERO_F4  (UP_F4 + OUT_F4)          // 8,960,000
#define DOWN_B16 ((N_DOWN * C_DOWN) / 16)  // 320,000
#define SKIP_B16 ((N_UP * C_SKIP) / 16)    // 640,000
#define WD_ELEMS (K27 * C_DOWN * C_DOWN)   // 442,368
#define WC_ELEMS (K27 * C_OUT * C_CAT)     // 497,664
#define PREP_TOT (ZERO_F4 + DOWN_B16 + SKIP_B16 + WD_ELEMS + WC_ELEMS) // 10,860,032

__global__ void __launch_bounds__(256) prep_kernel(
    float4* __restrict__ out4,
    const float4* __restrict__ down4, const float4* __restrict__ skip4,
    const float* __restrict__ Wd, const float* __restrict__ Wc)
{
    const int P[16] = {0,1,8,9, 2,3,10,11, 4,5,12,13, 6,7,14,15};   // pi
    int i = blockIdx.x * 256 + threadIdx.x;
    if (i < ZERO_F4) {
        float4 z = make_float4(0.f, 0.f, 0.f, 0.f);
        if (i < UP_F4) reinterpret_cast<float4*>(g_up)[i] = z;
        else           out4[i - UP_F4] = z;
        return;
    }
    i -= ZERO_F4;
    if (i < DOWN_B16 + SKIP_B16) {             // fp16, pi-permuted 16-block
        const float4* s4; __half* dstH; int g16;
        if (i < DOWN_B16) { s4 = down4; dstH = g_downH; g16 = i; }
        else              { s4 = skip4; dstH = g_skH;   g16 = i - DOWN_B16; }
        float v[16];
        float4 a = s4[4 * g16], b = s4[4 * g16 + 1],
               c = s4[4 * g16 + 2], d = s4[4 * g16 + 3];
        v[0]=a.x; v[1]=a.y; v[2]=a.z; v[3]=a.w;
        v[4]=b.x; v[5]=b.y; v[6]=b.z; v[7]=b.w;
        v[8]=c.x; v[9]=c.y; v[10]=c.z; v[11]=c.w;
        v[12]=d.x; v[13]=d.y; v[14]=d.z; v[15]=d.w;
        uint32_t r[8];
#pragma unroll
        for (int j = 0; j < 8; j++) r[j] = pack_h2(v[P[2*j]], v[P[2*j+1]]);
        uint4* o = (uint4*)((char*)dstH + (size_t)g16 * 32);
        o[0] = make_uint4(r[0], r[1], r[2], r[3]);
        o[1] = make_uint4(r[4], r[5], r[6], r[7]);
        return;
    }
    i -= DOWN_B16 + SKIP_B16;
    if (i < WD_ELEMS) {
        int k = i / (C_DOWN * C_DOWN), r = i % (C_DOWN * C_DOWN);
        int n = r / C_DOWN, p = r % C_DOWN;
        int pp = (p & ~15) + P[p & 15];
        int nn = (n & ~15) + P[n & 15];
        g_WdH[i] = __float2half_rn(Wd[((size_t)k * C_DOWN + pp) * C_DOWN + nn]);
    } else {
        int j = i - WD_ELEMS;
        int k = j / (C_OUT * C_CAT), r = j % (C_OUT * C_CAT);
        int n = r / C_CAT, p = r % C_CAT;
        int pp = (p & ~15) + P[p & 15];
        g_WcH[j] = __float2half_rn(Wc[((size_t)k * C_CAT + pp) * C_OUT + n]);
    }
}

// relu + fp16 (g_up is already pi-ordered; no permutation needed)
#define UP_B16 ((N_UP * C_DOWN) / 16)              // 1,280,000
__global__ void __launch_bounds__(256) relu_half_up_kernel() {
    int i = blockIdx.x * 256 + threadIdx.x;
    const float4* in4 = (const float4*)g_up + 4 * (size_t)i;
    uint32_t r[8];
#pragma unroll
    for (int j = 0; j < 4; j++) {
        float4 v = in4[j];
        r[2*j]   = pack_h2(fmaxf(v.x, 0.f), fmaxf(v.y, 0.f));
        r[2*j+1] = pack_h2(fmaxf(v.z, 0.f), fmaxf(v.w, 0.f));
    }
    uint4* o = (uint4*)((char*)g_upH + (size_t)i * 32);
    o[0] = make_uint4(r[0], r[1], r[2], r[3]);
    o[1] = make_uint4(r[4], r[5], r[6], r[7]);
}

// ---------------------------------------------------------------------------
// Deconv MMA (fp16, R15 unchanged): 2 K-phases of 64 halves, dbl-buf,
// pi LDS.64 fragments, row stride 144 B. 256 threads, 8 warps, warp tile
// 32x64. D staged f32 at stride 132, v4 red scatter. 2 CTAs/SM.
// ---------------------------------------------------------------------------
#define DH_ROWB 144
#define DA_B    (128 * DH_ROWB)            // 18432 B
#define D_IDX_B (4 * DA_B)                 // 73728 B
#define D_DP    132
#define D_SMEM  (D_IDX_B + 1024)           // 74752 B

__global__ void __launch_bounds__(256, 2)
deconv_mma_kernel(const int* __restrict__ iin, const int* __restrict__ iout)
{
    extern __shared__ __align__(16) char smd[];
    float* sm = (float*)smd;
    const uint32_t sbase = smem_u32(smd);
    int* iidx = (int*)(smd + D_IDX_B);
    int* oidx = iidx + 128;

    const int tid = threadIdx.x, wid = tid >> 5, lane = tid & 31;
    const int g = lane >> 2, t4 = lane & 3;
    const int k = blockIdx.y;
    const int ebase = blockIdx.x * 128;
    const int nvalid = min(128, N_DOWN - ebase);

    const int* pin  = iin  + (size_t)k * N_DOWN + ebase;
    const int* pout = iout + (size_t)k * N_DOWN + ebase;
    if (tid < 128) {
        iidx[tid] = (tid < nvalid) ? pin[tid] : pin[0];
        oidx[tid] = (tid < nvalid) ? pout[tid] : -1;
    }
    __syncthreads();

    const char* WdHk = (const char*)g_WdH + (size_t)k * C_DOWN * C_DOWN * 2;
    const char* DnH  = (const char*)g_downH;
    const int mbase = (wid & 3) * 32;
    const int nbase = (wid >> 2) * 64;

    const int e8 = tid >> 3, sub16 = (tid & 7) * 16;
    uint32_t asrc[4], bsrc[4], cdst[4];
#pragma unroll
    for (int i = 0; i < 4; i++) {
        int e = e8 + 32 * i;
        asrc[i] = (uint32_t)iidx[e] * 256u;
        bsrc[i] = (uint32_t)e * 256u;
        cdst[i] = (uint32_t)e * DH_ROWB + sub16;
    }

    auto issue = [&](int p, int buf) {
        uint32_t aB = sbase + buf * DA_B;
        uint32_t bB = sbase + (2 + buf) * DA_B;
        const char* as = DnH  + p * 128 + sub16;
        const char* bs = WdHk + p * 128 + sub16;
#pragma unroll
        for (int i = 0; i < 4; i++) cp_async16(aB + cdst[i], as + asrc[i]);
#pragma unroll
        for (int i = 0; i < 4; i++) cp_async16(bB + cdst[i], bs + bsrc[i]);
        CP_COMMIT();
    };

    issue(0, 0);

    float c[2][8][4] = {};
#pragma unroll
    for (int p = 0; p < 2; p++) {
        CP_WAIT(0);
        __syncthreads();
        if (p < 1) issue(1, 1);

        const char* Ab = smd + (p & 1) * DA_B + (mbase + g) * DH_ROWB + t4 * 8;
        const char* Bb = smd + (2 + (p & 1)) * DA_B + (nbase + g) * DH_ROWB + t4 * 8;
#pragma unroll
        for (int s = 0; s < 4; s++) {
            const int kb = s * 32;
            uint2 au[2], al[2];
#pragma unroll
            for (int mt = 0; mt < 2; mt++) {
                au[mt] = *(const uint2*)(Ab + mt * 16 * DH_ROWB + kb);
                al[mt] = *(const uint2*)(Ab + (mt * 16 + 8) * DH_ROWB + kb);
            }
#pragma unroll
            for (int j = 0; j < 8; j++) {
                uint2 b = *(const uint2*)(Bb + j * 8 * DH_ROWB + kb);
                mma_f16(c[0][j], au[0].x, al[0].x, au[0].y, al[0].y, b.x, b.y);
                mma_f16(c[1][j], au[1].x, al[1].x, au[1].y, al[1].y, b.x, b.y);
            }
        }
    }
    __syncthreads();

#pragma unroll
    for (int mt = 0; mt < 2; mt++) {
        int row = mbase + mt * 16 + g;
#pragma unroll
        for (int j = 0; j < 8; j++) {
            int col = nbase + j * 8 + 2 * t4;
            *(float2*)&sm[row * D_DP + col]       = make_float2(c[mt][j][0], c[mt][j][1]);
            *(float2*)&sm[(row + 8) * D_DP + col] = make_float2(c[mt][j][2], c[mt][j][3]);
        }
    }
    __syncthreads();

#pragma unroll
    for (int t = 0; t < 16; t++) {
        int f = tid + t * 256;
        int e = f >> 5, q = f & 31;
        int o = oidx[e];
        if (o >= 0) {
            float4 v = *(float4*)&sm[e * D_DP + q * 4];
            red_add_v4(g_up + (size_t)o * C_DOWN + q * 4, v);
        }
    }
}

// ---------------------------------------------------------------------------
// Conv MMA (fp16): D[128,96] = relu_cat[128,192] @ WcH[k]^T.
// 4 K-phases of 48 halves, **3-stage** cp.async ring (CP_WAIT(1), issue p+2),
// pi LDS.64, row stride 96 B. 128 threads, 4 warps, fat warp tile 64x48,
// c[4][6][4]=96 regs. D staged at stride 100, v4 red scatter.
// grid=(1250,27), 3 CTAs/SM (65.5 KB).
// ---------------------------------------------------------------------------
#define CH_ROWB  96
#define CA_B     (128 * CH_ROWB)           // 12288 B
#define CB_B     (96 * CH_ROWB)            // 9216 B
#define C_STG_B  (CA_B + CB_B)             // 21504 B per stage (%128 == 0)
#define C_DP     100
#define C_IDX_B  (3 * C_STG_B)             // 64512 B
#define C_SMEM   (C_IDX_B + 1024)          // 65536 B

__global__ void __launch_bounds__(128, 3)
conv_mma_kernel(const int* __restrict__ iin, const int* __restrict__ iout,
                float* __restrict__ out)
{
    extern __shared__ __align__(16) char smc[];
    float* sm = (float*)smc;
    const uint32_t sbase = smem_u32(smc);
    int* iidx = (int*)(smc + C_IDX_B);
    int* oidx = iidx + 128;

    const int tid = threadIdx.x, wid = tid >> 5, lane = tid & 31;
    const int g = lane >> 2, t4 = lane & 3;
    const int k = blockIdx.y;
    const int ebase = blockIdx.x * 128;

    const int* pin  = iin  + (size_t)k * N_UP + ebase;
    const int* pout = iout + (size_t)k * N_UP + ebase;
    iidx[tid] = pin[tid];
    oidx[tid] = pout[tid];
    __syncthreads();

    const char* WcHk = (const char*)g_WcH + (size_t)k * C_OUT * C_CAT * 2;
    const char* UpH  = (const char*)g_upH;
    const char* SkH  = (const char*)g_skH;
    const int mbase = (wid & 1) * 64;
    const int nbase = (wid >> 1) * 48;

    uint32_t aoffU[6], adst[6]; int cAoff[6];
#pragma unroll
    for (int i = 0; i < 6; i++) {
        int ch = tid + i * 128;
        int e = ch / 6, c = ch % 6;
        aoffU[i] = (uint32_t)iidx[e] * 256u;
        adst[i]  = (uint32_t)e * CH_ROWB + c * 16;
        cAoff[i] = c * 16;
    }
    uint32_t bsrc[5], bdst[5];
#pragma unroll
    for (int i = 0; i < 5; i++) {
        int ch = tid + i * 128;
        if (ch < 576) {
            int n = ch / 6, c = ch % 6;
            bsrc[i] = (uint32_t)n * 384 + c * 16;
            bdst[i] = (uint32_t)n * CH_ROWB + c * 16;
        } else bsrc[i] = 0xFFFFFFFFu;
    }

    auto issue = [&](int p, int buf) {
        uint32_t aB = sbase + buf * C_STG_B;
        uint32_t bB = aB + CA_B;
        const int pb = p * 96;
#pragma unroll
        for (int i = 0; i < 6; i++) {
            int sb = pb + cAoff[i];
            const char* src = (sb < 256) ? UpH + aoffU[i] + sb
                                         : SkH + (aoffU[i] >> 1) + (sb - 256);
            cp_async16(aB + adst[i], src);
        }
#pragma unroll
        for (int i = 0; i < 5; i++)
            if (bsrc[i] != 0xFFFFFFFFu)
                cp_async16(bB + bdst[i], WcHk + bsrc[i] + pb);
        CP_COMMIT();
    };

    issue(0, 0);
    issue(1, 1);

    float c[4][6][4] = {};
#pragma unroll
    for (int p = 0; p < 4; p++) {
        if (p < 3) CP_WAIT(1); else CP_WAIT(0);   // oldest group (phase p) landed
        __syncthreads();          // + all threads done with compute(p-1)
        if (p < 2) issue(p + 2, (p + 2) % 3);

        const char* Ab = smc + (p % 3) * C_STG_B + (mbase + g) * CH_ROWB + t4 * 8;
        const char* Bb = smc + (p % 3) * C_STG_B + CA_B + (nbase + g) * CH_ROWB + t4 * 8;
#pragma unroll
        for (int s = 0; s < 3; s++) {
            const int kb = s * 32;
            uint2 au[4], al[4];
#pragma unroll
            for (int mt = 0; mt < 4; mt++) {
                au[mt] = *(const uint2*)(Ab + mt * 16 * CH_ROWB + kb);
                al[mt] = *(const uint2*)(Ab + (mt * 16 + 8) * CH_ROWB + kb);
            }
#pragma unroll
            for (int j = 0; j < 6; j++) {
                uint2 b = *(const uint2*)(Bb + j * 8 * CH_ROWB + kb);
#pragma unroll
                for (int mt = 0; mt < 4; mt++)
                    mma_f16(c[mt][j], au[mt].x, al[mt].x, au[mt].y, al[mt].y,
                            b.x, b.y);
            }
        }
    }
    __syncthreads();

    // Stage D (stride 100)
#pragma unroll
    for (int mt = 0; mt < 4; mt++) {
        int row = mbase + mt * 16 + g;
#pragma unroll
        for (int j = 0; j < 6; j++) {
            int col = nbase + j * 8 + 2 * t4;
            *(float2*)&sm[row * C_DP + col]       = make_float2(c[mt][j][0], c[mt][j][1]);
            *(float2*)&sm[(row + 8) * C_DP + col] = make_float2(c[mt][j][2], c[mt][j][3]);
        }
    }
    __syncthreads();

    // Scatter: 3072 f4, 24/thread
#pragma unroll
    for (int t = 0; t < 24; t++) {
        int f = tid + t * 128;
        int e = f / 24, q = f % 24;
        float4 v = *(float4*)&sm[e * C_DP + q * 4];
        red_add_v4(out + (size_t)oidx[e] * C_OUT + q * 4, v);
    }
}

// ---------------------------------------------------------------------------
// Final ReLU
// ---------------------------------------------------------------------------
__global__ void __launch_bounds__(256) relu_kernel(float4* __restrict__ out4) {
    int i = blockIdx.x * 256 + threadIdx.x;
    float4 v = out4[i];
    v.x = fmaxf(v.x, 0.f); v.y = fmaxf(v.y, 0.f);
    v.z = fmaxf(v.z, 0.f); v.w = fmaxf(v.w, 0.f);
    out4[i] = v;
}

// ---------------------------------------------------------------------------
// Launch
// ---------------------------------------------------------------------------
extern "C" void kernel_launch(void* const* d_in, const int* in_sizes, int n_in,
                              void* d_out, int out_size)
{
    const float* skip = nullptr; const float* down = nullptr;
    const float* Wd = nullptr;   const float* Wc = nullptr;
    const int *d_iin = nullptr, *d_iout = nullptr, *c_iin = nullptr, *c_iout = nullptr;

    for (int i = 0; i < n_in; i++) {
        int sz = in_sizes[i];
        if      (sz == N_UP * C_SKIP)         skip = (const float*)d_in[i];
        else if (sz == N_DOWN * C_DOWN)       down = (const float*)d_in[i];
        else if (sz == K27 * C_DOWN * C_DOWN) Wd   = (const float*)d_in[i];
        else if (sz == K27 * C_CAT * C_OUT)   Wc   = (const float*)d_in[i];
        else if (sz == K27 * N_DOWN) { if (!d_iin) d_iin = (const int*)d_in[i]; else d_iout = (const int*)d_in[i]; }
        else if (sz == K27 * N_UP)   { if (!c_iin) c_iin = (const int*)d_in[i]; else c_iout = (const int*)d_in[i]; }
    }
    float* out = (float*)d_out;

    cudaFuncSetAttribute(deconv_mma_kernel, cudaFuncAttributeMaxDynamicSharedMemorySize, D_SMEM);
    cudaFuncSetAttribute(conv_mma_kernel,   cudaFuncAttributeMaxDynamicSharedMemorySize, C_SMEM);

    prep_kernel<<<PREP_TOT / 256, 256>>>((float4*)out, (const float4*)down,
                                         (const float4*)skip, Wd, Wc);
    deconv_mma_kernel<<<dim3((N_DOWN + 127) / 128, K27), 256, D_SMEM>>>(d_iin, d_iout);
    relu_half_up_kernel<<<UP_B16 / 256, 256>>>();
    conv_mma_kernel<<<dim3(N_UP / 128, K27), 128, C_SMEM>>>(c_iin, c_iout, out);
    relu_kernel<<<OUT_F4 / 256, 256>>>((float4*)out);
}